// round 3
// baseline (speedup 1.0000x reference)
#include <cuda_runtime.h>
#include <cstdint>

#define CD    256
#define NTOK  32768
#define KCB   8192
#define NELEM 8388608
#define NCHUNK 64

__device__ float g_sz[NTOK];
__device__ float g_en[KCB];
__device__ float g_pd[NTOK * NCHUNK];
__device__ int   g_pi[NTOK * NCHUNK];
__device__ int   g_idx[NTOK];
__device__ unsigned int g_hist[KCB];
__device__ double g_msep[8192];

// ---------------------------------------------------------------------------
// sz[n] = sum_c z[n,c]^2 with XLA:GPU-style warp row reduction:
// lane l sequentially accumulates c = l, l+32, ..., l+224 (mul then add,
// both rounded, no fma), then shfl.down tree with offsets 16,8,4,2,1.
// Block handles 8 consecutive tokens; loads staged via smem for coalescing.
// ---------------------------------------------------------------------------
__global__ __launch_bounds__(256) void k_sz(const float* __restrict__ z) {
    __shared__ float zt[CD][9];
    int n0 = blockIdx.x * 8;
    int b  = n0 >> 10;
    int hw0 = n0 & 1023;
    const float* zbase = z + (size_t)b * 262144 + hw0;

    int wpos  = threadIdx.x & 7;
    int cbase = threadIdx.x >> 3;
    #pragma unroll
    for (int j = 0; j < 8; j++) {
        int c = cbase + 32 * j;
        zt[c][wpos] = zbase[(size_t)c * 1024 + wpos];
    }
    __syncthreads();

    int warp = threadIdx.x >> 5;
    int lane = threadIdx.x & 31;
    float p = 0.0f;
    #pragma unroll
    for (int j = 0; j < 8; j++) {
        float v = zt[lane + 32 * j][warp];
        p = __fadd_rn(p, __fmul_rn(v, v));
    }
    #pragma unroll
    for (int off = 16; off >= 1; off >>= 1)
        p = __fadd_rn(p, __shfl_down_sync(0xffffffffu, p, off));
    if (lane == 0) g_sz[n0 + warp] = p;
}

// ---------------------------------------------------------------------------
// en[k] = sum_c e[k,c]^2 (order-insensitive: en ~ 1.3e-6, ulps ~1e-13).
// Also zeroes the histogram each call.
// ---------------------------------------------------------------------------
__global__ __launch_bounds__(256) void k_en(const float* __restrict__ e) {
    int gt = blockIdx.x * 256 + threadIdx.x;
    if (gt < KCB) g_hist[gt] = 0u;

    int warp = gt >> 5;
    int lane = gt & 31;
    if (warp < KCB) {
        const float* row = e + (size_t)warp * CD;
        float p = 0.0f;
        #pragma unroll
        for (int j = 0; j < 8; j++) {
            float v = row[lane + 32 * j];
            p = __fadd_rn(p, __fmul_rn(v, v));
        }
        #pragma unroll
        for (int off = 16; off >= 1; off >>= 1)
            p = __fadd_rn(p, __shfl_down_sync(0xffffffffu, p, off));
        if (lane == 0) g_en[warp] = p;
    }
}

// ---------------------------------------------------------------------------
// Fused distance GEMM + per-chunk argmin.
// Block = 64 tokens x 128 codes; 256 threads, 4x8 micro-tile per thread.
// Accumulator per output: single __fmaf_rn chain, c ascending 0..255
// (replicates Eigen gebp / cuBLAS SIMT sgemm accumulation order).
// Epilogue: d = fl(fl(sz - 2m) + en), argmin with first-index tie-break.
// ---------------------------------------------------------------------------
__global__ __launch_bounds__(256) void k_dist(const float* __restrict__ z,
                                              const float* __restrict__ e) {
    __shared__ float zs[32][64];
    __shared__ float es[32][132];
    __shared__ float sd[64][17];
    __shared__ int   si[64][17];

    int tid = threadIdx.x;
    int n0 = blockIdx.x * 128;   // code tile
    int m0 = blockIdx.y * 64;    // token tile
    int b  = m0 >> 10;
    int hw0 = m0 & 1023;
    const float* zbase = z + (size_t)b * 262144 + hw0;

    float acc[4][8];
    #pragma unroll
    for (int i = 0; i < 4; i++)
        #pragma unroll
        for (int j = 0; j < 8; j++) acc[i][j] = 0.0f;

    int ty = tid >> 4, tx = tid & 15;
    int zn = tid & 63, zc = tid >> 6;     // z loader: n fast, 4 c per pass
    int enr = tid >> 3, ec4 = tid & 7;    // e loader: float4 along c

    for (int ct = 0; ct < 8; ct++) {
        int c0 = ct * 32;
        #pragma unroll
        for (int p = 0; p < 8; p++) {
            int c = zc + 4 * p;
            zs[c][zn] = zbase[(size_t)(c0 + c) * 1024 + zn];
        }
        #pragma unroll
        for (int p = 0; p < 4; p++) {
            int nn = enr + 32 * p;
            float4 v = *(const float4*)&e[(size_t)(n0 + nn) * CD + c0 + 4 * ec4];
            es[4 * ec4 + 0][nn] = v.x;
            es[4 * ec4 + 1][nn] = v.y;
            es[4 * ec4 + 2][nn] = v.z;
            es[4 * ec4 + 3][nn] = v.w;
        }
        __syncthreads();

        #pragma unroll
        for (int kk = 0; kk < 32; kk++) {
            float4 a  = *(const float4*)&zs[kk][ty * 4];
            float4 b0 = *(const float4*)&es[kk][tx * 8];
            float4 b1 = *(const float4*)&es[kk][tx * 8 + 4];
            float av[4] = {a.x, a.y, a.z, a.w};
            float bv[8] = {b0.x, b0.y, b0.z, b0.w, b1.x, b1.y, b1.z, b1.w};
            #pragma unroll
            for (int i = 0; i < 4; i++)
                #pragma unroll
                for (int j = 0; j < 8; j++)
                    acc[i][j] = __fmaf_rn(av[i], bv[j], acc[i][j]);
        }
        __syncthreads();
    }

    #pragma unroll
    for (int i = 0; i < 4; i++) {
        int gm = m0 + ty * 4 + i;
        float sz = g_sz[gm];
        float bd = 0.0f;
        int   bi = -1;
        #pragma unroll
        for (int j = 0; j < 8; j++) {
            int gn = n0 + tx * 8 + j;
            float d = __fadd_rn(__fsub_rn(sz, __fmul_rn(2.0f, acc[i][j])), g_en[gn]);
            if (bi < 0 || d < bd) { bd = d; bi = gn; }  // j ascending: ties keep lower idx
        }
        sd[ty * 4 + i][tx] = bd;
        si[ty * 4 + i][tx] = bi;
    }
    __syncthreads();

    if (tid < 64) {
        float bd = sd[tid][0];
        int   bi = si[tid][0];
        #pragma unroll
        for (int t = 1; t < 16; t++) {
            float d = sd[tid][t];
            if (d < bd) { bd = d; bi = si[tid][t]; }  // tx ascending = idx ascending
        }
        int gm = m0 + tid;
        g_pd[(size_t)gm * NCHUNK + blockIdx.x] = bd;
        g_pi[(size_t)gm * NCHUNK + blockIdx.x] = bi;
    }
}

// ---------------------------------------------------------------------------
// Reduce 64 chunk candidates per token (chunks ascending -> lower index on
// tie), write final index, histogram, and (optionally) float indices output.
// ---------------------------------------------------------------------------
__global__ __launch_bounds__(256) void k_reduce(float* __restrict__ out_idx,
                                                int write_idx) {
    int n = blockIdx.x * 256 + threadIdx.x;
    if (n >= NTOK) return;
    const float* pd = g_pd + (size_t)n * NCHUNK;
    const int*   pi = g_pi + (size_t)n * NCHUNK;
    float bd = pd[0];
    int   bi = pi[0];
    #pragma unroll 8
    for (int c = 1; c < NCHUNK; c++) {
        float d = pd[c];
        if (d < bd) { bd = d; bi = pi[c]; }
    }
    g_idx[n] = bi;
    atomicAdd(&g_hist[bi], 1u);
    if (write_idx) out_idx[n] = (float)bi;
}

// ---------------------------------------------------------------------------
// z_q_st = fl(z + fl(z_q - z)) elementwise; per-block mse partial in double.
// ---------------------------------------------------------------------------
__global__ __launch_bounds__(1024) void k_zq(const float* __restrict__ z,
                                             const float* __restrict__ e,
                                             float* __restrict__ out) {
    __shared__ double red[1024];
    int f = blockIdx.x * 1024 + threadIdx.x;
    int bc = f >> 10;
    int hw = f & 1023;
    int bb = bc >> 8;
    int c  = bc & 255;
    int n  = bb * 1024 + hw;

    float zv = z[f];
    float zq = e[(size_t)g_idx[n] * CD + c];
    float t  = __fsub_rn(zq, zv);
    out[f]   = __fadd_rn(zv, t);
    float dm = __fsub_rn(zv, zq);
    red[threadIdx.x] = (double)dm * (double)dm;
    __syncthreads();
    for (int s = 512; s >= 1; s >>= 1) {
        if (threadIdx.x < s) red[threadIdx.x] += red[threadIdx.x + s];
        __syncthreads();
    }
    if (threadIdx.x == 0) g_msep[blockIdx.x] = red[0];
}

// ---------------------------------------------------------------------------
// Finalize: mse -> vq_loss, histogram -> perplexity. Deterministic.
// ---------------------------------------------------------------------------
__global__ __launch_bounds__(256) void k_final(float* __restrict__ out_scalars) {
    __shared__ double red[256];
    int t = threadIdx.x;

    double s = 0.0;
    for (int i = t; i < 8192; i += 256) s += g_msep[i];
    red[t] = s;
    __syncthreads();
    for (int st = 128; st >= 1; st >>= 1) {
        if (t < st) red[t] += red[t + st];
        __syncthreads();
    }
    double mse = red[0] / (double)NELEM;

    double ent = 0.0;
    for (int k = t; k < KCB; k += 256) {
        unsigned int c = g_hist[k];
        if (c) {
            double p = (double)c / (double)NTOK;
            ent += p * log(p);
        }
    }
    __syncthreads();
    red[t] = ent;
    __syncthreads();
    for (int st = 128; st >= 1; st >>= 1) {
        if (t < st) red[t] += red[t + st];
        __syncthreads();
    }
    if (t == 0) {
        out_scalars[0] = __fmul_rn(1.25f, (float)mse);   // (1 + cc) * mse
        out_scalars[1] = (float)exp(-red[0]);            // perplexity
    }
}

extern "C" void kernel_launch(void* const* d_in, const int* in_sizes, int n_in,
                              void* d_out, int out_size) {
    const float* z = (const float*)d_in[0];   // z_e  [32,256,32,32]
    const float* e = (const float*)d_in[1];   // emb_w [8192,256]
    float* out = (float*)d_out;

    // Assumed layout: [z_q_st (8388608) | vq_loss | perplexity | indices (32768)]
    int full = (out_size >= NELEM + 2 + NTOK) ? 1 : 0;
    float* out_scalars = out + NELEM;
    float* out_idx     = out + NELEM + 2;

    k_sz<<<NTOK / 8, 256>>>(z);
    k_en<<<KCB * 32 / 256, 256>>>(e);
    {
        dim3 grid(KCB / 128, NTOK / 64);
        k_dist<<<grid, 256>>>(z, e);
    }
    k_reduce<<<NTOK / 256, 256>>>(full ? out_idx : (float*)d_out, full);
    k_zq<<<NELEM / 1024, 1024>>>(z, e, out);
    if (full) k_final<<<1, 256>>>(out_scalars);
}

// round 6
// speedup vs baseline: 1.6276x; 1.6276x over previous
#include <cuda_runtime.h>
#include <cstdint>

#define CD    256
#define NTOK  32768
#define KCB   8192
#define NELEM 8388608
#define NCHUNK 64

__device__ float g_sz[NTOK];
__device__ float g_en[KCB];
__device__ float g_pd[NTOK * NCHUNK];
__device__ int   g_pi[NTOK * NCHUNK];
__device__ int   g_idx[NTOK];
__device__ unsigned int g_hist[KCB];
__device__ double g_msep[8192];

// ---- packed f32x2 helpers (FFMA2: two independent IEEE fp32 FMA lanes) ----
__device__ __forceinline__ unsigned long long pack_dup(float x) {
    unsigned long long r;
    asm("mov.b64 %0, {%1, %1};" : "=l"(r) : "f"(x));
    return r;
}
__device__ __forceinline__ void fma2(unsigned long long& d,
                                     unsigned long long a,
                                     unsigned long long b) {
    asm("fma.rn.f32x2 %0, %1, %2, %0;" : "+l"(d) : "l"(a), "l"(b));
}
__device__ __forceinline__ void unpack2(unsigned long long v, float& lo, float& hi) {
    asm("mov.b64 {%0, %1}, %2;" : "=f"(lo), "=f"(hi) : "l"(v));
}

// ---------------------------------------------------------------------------
// sz[n] = sum_c z[n,c]^2 — XLA:GPU-style warp row reduction (FROZEN: bit-exact
// decision-path input). lane l sums c = l, l+32, ..., l+224 sequentially
// (separate mul/add, no fma), then shfl.down tree 16,8,4,2,1.
// ---------------------------------------------------------------------------
__global__ __launch_bounds__(256) void k_sz(const float* __restrict__ z) {
    __shared__ float zt[CD][9];
    int n0 = blockIdx.x * 8;
    int b  = n0 >> 10;
    int hw0 = n0 & 1023;
    const float* zbase = z + (size_t)b * 262144 + hw0;

    int wpos  = threadIdx.x & 7;
    int cbase = threadIdx.x >> 3;
    #pragma unroll
    for (int j = 0; j < 8; j++) {
        int c = cbase + 32 * j;
        zt[c][wpos] = zbase[(size_t)c * 1024 + wpos];
    }
    __syncthreads();

    int warp = threadIdx.x >> 5;
    int lane = threadIdx.x & 31;
    float p = 0.0f;
    #pragma unroll
    for (int j = 0; j < 8; j++) {
        float v = zt[lane + 32 * j][warp];
        p = __fadd_rn(p, __fmul_rn(v, v));
    }
    #pragma unroll
    for (int off = 16; off >= 1; off >>= 1)
        p = __fadd_rn(p, __shfl_down_sync(0xffffffffu, p, off));
    if (lane == 0) g_sz[n0 + warp] = p;
}

// ---------------------------------------------------------------------------
// en[k] = sum_c e[k,c]^2 (same reduction shape; also zeroes histogram).
// ---------------------------------------------------------------------------
__global__ __launch_bounds__(256) void k_en(const float* __restrict__ e) {
    int gt = blockIdx.x * 256 + threadIdx.x;
    if (gt < KCB) g_hist[gt] = 0u;

    int warp = gt >> 5;
    int lane = gt & 31;
    if (warp < KCB) {
        const float* row = e + (size_t)warp * CD;
        float p = 0.0f;
        #pragma unroll
        for (int j = 0; j < 8; j++) {
            float v = row[lane + 32 * j];
            p = __fadd_rn(p, __fmul_rn(v, v));
        }
        #pragma unroll
        for (int off = 16; off >= 1; off >>= 1)
            p = __fadd_rn(p, __shfl_down_sync(0xffffffffu, p, off));
        if (lane == 0) g_en[warp] = p;
    }
}

// ---------------------------------------------------------------------------
// Fused distance GEMM + per-chunk argmin, FFMA2 mainloop.
// Block = 64 tokens x 128 codes, 256 threads, 4x8 micro-tile per thread.
// Per-(n,k) accumulation: single fma chain, c ascending 0..255 — each f32x2
// lane is its own chain, bitwise identical to scalar __fmaf_rn. (FROZEN)
// Thread tx owns code columns {2tx, 2tx+1, 2tx+32, 2tx+33, ...} so b-operand
// LDS.64 loads are bank-conflict-free; es stores XOR-swizzled (phys=n^(c&28))
// so the transposed fill is conflict-free too.
// Argmin: lexicographic (d, idx) min == exact first-occurrence argmin.
// ---------------------------------------------------------------------------
__global__ __launch_bounds__(256, 2) void k_dist(const float* __restrict__ z,
                                                 const float* __restrict__ e) {
    __shared__ __align__(16) float zs[2][32][64];    // 16 KB
    __shared__ __align__(16) float es[2][32][128];   // 32 KB  (total 48 KB)

    int tid = threadIdx.x;
    int n0 = blockIdx.x * 128;   // code tile
    int m0 = blockIdx.y * 64;    // token tile
    int b  = m0 >> 10;
    int hw0 = m0 & 1023;
    const float* zbase = z + (size_t)b * 262144 + hw0;

    unsigned long long acc2[4][4];
    #pragma unroll
    for (int i = 0; i < 4; i++)
        #pragma unroll
        for (int q = 0; q < 4; q++) acc2[i][q] = 0ull;

    int ty = tid >> 4, tx = tid & 15;
    int zn = tid & 63, zc = tid >> 6;     // z loader
    int enr = tid >> 3, ec4 = tid & 7;    // e loader (float4 along c)
    int swd = 4 * ec4;                    // store-side swizzle = (c & 28)

    float  zr[8];
    float4 er[4];

    // prologue: chunk 0 -> buffer 0
    #pragma unroll
    for (int p = 0; p < 8; p++)
        zr[p] = zbase[(size_t)(zc + 4 * p) * 1024 + zn];
    #pragma unroll
    for (int p = 0; p < 4; p++)
        er[p] = *(const float4*)&e[(size_t)(n0 + enr + 32 * p) * CD + 4 * ec4];
    #pragma unroll
    for (int p = 0; p < 8; p++)
        zs[0][zc + 4 * p][zn] = zr[p];
    #pragma unroll
    for (int p = 0; p < 4; p++) {
        int nn = (enr + 32 * p) ^ swd;
        es[0][4 * ec4 + 0][nn] = er[p].x;
        es[0][4 * ec4 + 1][nn] = er[p].y;
        es[0][4 * ec4 + 2][nn] = er[p].z;
        es[0][4 * ec4 + 3][nn] = er[p].w;
    }
    __syncthreads();

    for (int ct = 0; ct < 8; ct++) {
        int cur = ct & 1;
        if (ct < 7) {
            int c0 = (ct + 1) * 32;
            #pragma unroll
            for (int p = 0; p < 8; p++)
                zr[p] = zbase[(size_t)(c0 + zc + 4 * p) * 1024 + zn];
            #pragma unroll
            for (int p = 0; p < 4; p++)
                er[p] = *(const float4*)&e[(size_t)(n0 + enr + 32 * p) * CD + c0 + 4 * ec4];
        }

        #pragma unroll
        for (int kk = 0; kk < 32; kk++) {
            float4 a = *(const float4*)&zs[cur][kk][ty * 4];
            unsigned long long av0 = pack_dup(a.x);
            unsigned long long av1 = pack_dup(a.y);
            unsigned long long av2v = pack_dup(a.z);
            unsigned long long av3 = pack_dup(a.w);
            const float* erow = &es[cur][kk][0];
            int i0 = (2 * tx) ^ (kk & 28);
            unsigned long long bv0 = *(const unsigned long long*)(erow + i0);
            unsigned long long bv1 = *(const unsigned long long*)(erow + i0 + 32);
            unsigned long long bv2 = *(const unsigned long long*)(erow + i0 + 64);
            unsigned long long bv3 = *(const unsigned long long*)(erow + i0 + 96);
            fma2(acc2[0][0], av0, bv0); fma2(acc2[0][1], av0, bv1);
            fma2(acc2[0][2], av0, bv2); fma2(acc2[0][3], av0, bv3);
            fma2(acc2[1][0], av1, bv0); fma2(acc2[1][1], av1, bv1);
            fma2(acc2[1][2], av1, bv2); fma2(acc2[1][3], av1, bv3);
            fma2(acc2[2][0], av2v, bv0); fma2(acc2[2][1], av2v, bv1);
            fma2(acc2[2][2], av2v, bv2); fma2(acc2[2][3], av2v, bv3);
            fma2(acc2[3][0], av3, bv0); fma2(acc2[3][1], av3, bv1);
            fma2(acc2[3][2], av3, bv2); fma2(acc2[3][3], av3, bv3);
        }

        if (ct < 7) {
            int nxt = cur ^ 1;
            #pragma unroll
            for (int p = 0; p < 8; p++)
                zs[nxt][zc + 4 * p][zn] = zr[p];
            #pragma unroll
            for (int p = 0; p < 4; p++) {
                int nn = (enr + 32 * p) ^ swd;
                es[nxt][4 * ec4 + 0][nn] = er[p].x;
                es[nxt][4 * ec4 + 1][nn] = er[p].y;
                es[nxt][4 * ec4 + 2][nn] = er[p].z;
                es[nxt][4 * ec4 + 3][nn] = er[p].w;
            }
        }
        __syncthreads();
    }

    // epilogue: d = fl(fl(sz - 2m) + en), lexicographic argmin.  (FROZEN math)
    float* sdp = (float*)&zs[0][0][0];   // reuse smem (all compute done)
    int*   sip = (int*)&zs[1][0][0];

    #pragma unroll
    for (int i = 0; i < 4; i++) {
        int gm = m0 + ty * 4 + i;
        float szv = g_sz[gm];
        float bd = 3.402823466e+38f;
        int   bi = 0x7fffffff;
        #pragma unroll
        for (int q = 0; q < 4; q++) {
            float mlo, mhi;
            unpack2(acc2[i][q], mlo, mhi);
            int gn = n0 + 2 * tx + 32 * q;
            float dlo = __fadd_rn(__fsub_rn(szv, __fmul_rn(2.0f, mlo)), g_en[gn]);
            if (dlo < bd || (dlo == bd && gn < bi)) { bd = dlo; bi = gn; }
            float dhi = __fadd_rn(__fsub_rn(szv, __fmul_rn(2.0f, mhi)), g_en[gn + 1]);
            if (dhi < bd || (dhi == bd && gn + 1 < bi)) { bd = dhi; bi = gn + 1; }
        }
        sdp[(ty * 4 + i) * 17 + tx] = bd;
        sip[(ty * 4 + i) * 17 + tx] = bi;
    }
    __syncthreads();

    if (tid < 64) {
        float bd = sdp[tid * 17];
        int   bi = sip[tid * 17];
        #pragma unroll
        for (int t = 1; t < 16; t++) {
            float d  = sdp[tid * 17 + t];
            int   ii = sip[tid * 17 + t];
            if (d < bd || (d == bd && ii < bi)) { bd = d; bi = ii; }
        }
        int gm = m0 + tid;
        g_pd[(size_t)gm * NCHUNK + blockIdx.x] = bd;
        g_pi[(size_t)gm * NCHUNK + blockIdx.x] = bi;
    }
}

// ---------------------------------------------------------------------------
// Reduce 64 chunk candidates per token (chunks ascending => lower index wins
// ties via strict <), write index, histogram, float indices output.
// ---------------------------------------------------------------------------
__global__ __launch_bounds__(256) void k_reduce(float* __restrict__ out_idx,
                                                int write_idx) {
    int n = blockIdx.x * 256 + threadIdx.x;
    if (n >= NTOK) return;
    const float* pd = g_pd + (size_t)n * NCHUNK;
    const int*   pi = g_pi + (size_t)n * NCHUNK;
    float bd = pd[0];
    int   bi = pi[0];
    #pragma unroll 8
    for (int c = 1; c < NCHUNK; c++) {
        float d = pd[c];
        if (d < bd) { bd = d; bi = pi[c]; }
    }
    g_idx[n] = bi;
    atomicAdd(&g_hist[bi], 1u);
    if (write_idx) out_idx[n] = (float)bi;
}

// ---------------------------------------------------------------------------
// z_q_st = fl(z + fl(z_q - z)); per-block mse partial in double.
// ---------------------------------------------------------------------------
__global__ __launch_bounds__(1024) void k_zq(const float* __restrict__ z,
                                             const float* __restrict__ e,
                                             float* __restrict__ out) {
    __shared__ double red[1024];
    int f = blockIdx.x * 1024 + threadIdx.x;
    int bc = f >> 10;
    int hw = f & 1023;
    int bb = bc >> 8;
    int c  = bc & 255;
    int n  = bb * 1024 + hw;

    float zv = z[f];
    float zq = e[(size_t)g_idx[n] * CD + c];
    float t  = __fsub_rn(zq, zv);
    out[f]   = __fadd_rn(zv, t);
    float dm = __fsub_rn(zv, zq);
    red[threadIdx.x] = (double)dm * (double)dm;
    __syncthreads();
    for (int s = 512; s >= 1; s >>= 1) {
        if (threadIdx.x < s) red[threadIdx.x] += red[threadIdx.x + s];
        __syncthreads();
    }
    if (threadIdx.x == 0) g_msep[blockIdx.x] = red[0];
}

// ---------------------------------------------------------------------------
// Finalize: mse -> vq_loss, histogram -> perplexity. Deterministic.
// ---------------------------------------------------------------------------
__global__ __launch_bounds__(256) void k_final(float* __restrict__ out_scalars) {
    __shared__ double red[256];
    int t = threadIdx.x;

    double s = 0.0;
    for (int i = t; i < 8192; i += 256) s += g_msep[i];
    red[t] = s;
    __syncthreads();
    for (int st = 128; st >= 1; st >>= 1) {
        if (t < st) red[t] += red[t + st];
        __syncthreads();
    }
    double mse = red[0] / (double)NELEM;

    double ent = 0.0;
    for (int k = t; k < KCB; k += 256) {
        unsigned int c = g_hist[k];
        if (c) {
            double p = (double)c / (double)NTOK;
            ent += p * log(p);
        }
    }
    __syncthreads();
    red[t] = ent;
    __syncthreads();
    for (int st = 128; st >= 1; st >>= 1) {
        if (t < st) red[t] += red[t + st];
        __syncthreads();
    }
    if (t == 0) {
        out_scalars[0] = __fmul_rn(1.25f, (float)mse);   // (1 + cc) * mse
        out_scalars[1] = (float)exp(-red[0]);            // perplexity
    }
}

extern "C" void kernel_launch(void* const* d_in, const int* in_sizes, int n_in,
                              void* d_out, int out_size) {
    const float* z = (const float*)d_in[0];   // z_e  [32,256,32,32]
    const float* e = (const float*)d_in[1];   // emb_w [8192,256]
    float* out = (float*)d_out;

    // Layout: [z_q_st (8388608) | vq_loss | perplexity | indices (32768)]
    int full = (out_size >= NELEM + 2 + NTOK) ? 1 : 0;
    float* out_scalars = out + NELEM;
    float* out_idx     = out + NELEM + 2;

    k_sz<<<NTOK / 8, 256>>>(z);
    k_en<<<KCB * 32 / 256, 256>>>(e);
    {
        dim3 grid(KCB / 128, NTOK / 64);
        k_dist<<<grid, 256>>>(z, e);
    }
    k_reduce<<<NTOK / 256, 256>>>(full ? out_idx : (float*)d_out, full);
    k_zq<<<NELEM / 1024, 1024>>>(z, e, out);
    if (full) k_final<<<1, 256>>>(out_scalars);
}

// round 7
// speedup vs baseline: 1.6280x; 1.0003x over previous
#include <cuda_runtime.h>
#include <cstdint>

#define CD    256
#define NTOK  32768
#define KCB   8192
#define NELEM 8388608
#define NCHUNK 64

__device__ float g_sz[NTOK];
__device__ float g_en[KCB];
__device__ float g_pd[NTOK * NCHUNK];
__device__ int   g_pi[NTOK * NCHUNK];
__device__ int   g_idx[NTOK];
__device__ unsigned int g_hist[KCB];
__device__ double g_msep[8192];

// ---- packed f32x2 helpers (FFMA2: two independent IEEE fp32 FMA lanes) ----
__device__ __forceinline__ unsigned long long pack_dup(float x) {
    unsigned long long r;
    asm("mov.b64 %0, {%1, %1};" : "=l"(r) : "f"(x));
    return r;
}
__device__ __forceinline__ void fma2(unsigned long long& d,
                                     unsigned long long a,
                                     unsigned long long b) {
    asm("fma.rn.f32x2 %0, %1, %2, %0;" : "+l"(d) : "l"(a), "l"(b));
}
__device__ __forceinline__ void unpack2(unsigned long long v, float& lo, float& hi) {
    asm("mov.b64 {%0, %1}, %2;" : "=f"(lo), "=f"(hi) : "l"(v));
}

// ---------------------------------------------------------------------------
// sz[n] = sum_c z[n,c]^2 — XLA:GPU-style warp row reduction (FROZEN: bit-exact
// decision-path input). lane l sums c = l, l+32, ..., l+224 sequentially
// (separate mul/add, no fma), then shfl.down tree 16,8,4,2,1.
// ---------------------------------------------------------------------------
__global__ __launch_bounds__(256) void k_sz(const float* __restrict__ z) {
    __shared__ float zt[CD][9];
    int n0 = blockIdx.x * 8;
    int b  = n0 >> 10;
    int hw0 = n0 & 1023;
    const float* zbase = z + (size_t)b * 262144 + hw0;

    int wpos  = threadIdx.x & 7;
    int cbase = threadIdx.x >> 3;
    #pragma unroll
    for (int j = 0; j < 8; j++) {
        int c = cbase + 32 * j;
        zt[c][wpos] = zbase[(size_t)c * 1024 + wpos];
    }
    __syncthreads();

    int warp = threadIdx.x >> 5;
    int lane = threadIdx.x & 31;
    float p = 0.0f;
    #pragma unroll
    for (int j = 0; j < 8; j++) {
        float v = zt[lane + 32 * j][warp];
        p = __fadd_rn(p, __fmul_rn(v, v));
    }
    #pragma unroll
    for (int off = 16; off >= 1; off >>= 1)
        p = __fadd_rn(p, __shfl_down_sync(0xffffffffu, p, off));
    if (lane == 0) g_sz[n0 + warp] = p;
}

// ---------------------------------------------------------------------------
// en[k] = sum_c e[k,c]^2 (same reduction shape; also zeroes histogram).
// ---------------------------------------------------------------------------
__global__ __launch_bounds__(256) void k_en(const float* __restrict__ e) {
    int gt = blockIdx.x * 256 + threadIdx.x;
    if (gt < KCB) g_hist[gt] = 0u;

    int warp = gt >> 5;
    int lane = gt & 31;
    if (warp < KCB) {
        const float* row = e + (size_t)warp * CD;
        float p = 0.0f;
        #pragma unroll
        for (int j = 0; j < 8; j++) {
            float v = row[lane + 32 * j];
            p = __fadd_rn(p, __fmul_rn(v, v));
        }
        #pragma unroll
        for (int off = 16; off >= 1; off >>= 1)
            p = __fadd_rn(p, __shfl_down_sync(0xffffffffu, p, off));
        if (lane == 0) g_en[warp] = p;
    }
}

// ---------------------------------------------------------------------------
// Fused distance GEMM + per-chunk argmin, FFMA2 mainloop.
// Block = 64 tokens x 128 codes, 256 threads, 4x8 micro-tile per thread.
// Per-(n,k) accumulation: single fma chain, c ascending 0..255 — each f32x2
// lane is its own chain, bitwise identical to scalar __fmaf_rn. (FROZEN)
// Thread tx owns code columns {2tx, 2tx+1, 2tx+32, 2tx+33, ...} so b-operand
// LDS.64 loads are bank-conflict-free; es stores XOR-swizzled (phys=n^(c&28))
// so the transposed fill is conflict-free too.
// Argmin: lexicographic (d, idx) min == exact first-occurrence argmin.
// ---------------------------------------------------------------------------
__global__ __launch_bounds__(256, 2) void k_dist(const float* __restrict__ z,
                                                 const float* __restrict__ e) {
    __shared__ __align__(16) float zs[2][32][64];    // 16 KB
    __shared__ __align__(16) float es[2][32][128];   // 32 KB  (total 48 KB)

    int tid = threadIdx.x;
    int n0 = blockIdx.x * 128;   // code tile
    int m0 = blockIdx.y * 64;    // token tile
    int b  = m0 >> 10;
    int hw0 = m0 & 1023;
    const float* zbase = z + (size_t)b * 262144 + hw0;

    unsigned long long acc2[4][4];
    #pragma unroll
    for (int i = 0; i < 4; i++)
        #pragma unroll
        for (int q = 0; q < 4; q++) acc2[i][q] = 0ull;

    int ty = tid >> 4, tx = tid & 15;
    int zn = tid & 63, zc = tid >> 6;     // z loader
    int enr = tid >> 3, ec4 = tid & 7;    // e loader (float4 along c)
    int swd = 4 * ec4;                    // store-side swizzle = (c & 28)

    float  zr[8];
    float4 er[4];

    // prologue: chunk 0 -> buffer 0
    #pragma unroll
    for (int p = 0; p < 8; p++)
        zr[p] = zbase[(size_t)(zc + 4 * p) * 1024 + zn];
    #pragma unroll
    for (int p = 0; p < 4; p++)
        er[p] = *(const float4*)&e[(size_t)(n0 + enr + 32 * p) * CD + 4 * ec4];
    #pragma unroll
    for (int p = 0; p < 8; p++)
        zs[0][zc + 4 * p][zn] = zr[p];
    #pragma unroll
    for (int p = 0; p < 4; p++) {
        int nn = (enr + 32 * p) ^ swd;
        es[0][4 * ec4 + 0][nn] = er[p].x;
        es[0][4 * ec4 + 1][nn] = er[p].y;
        es[0][4 * ec4 + 2][nn] = er[p].z;
        es[0][4 * ec4 + 3][nn] = er[p].w;
    }
    __syncthreads();

    for (int ct = 0; ct < 8; ct++) {
        int cur = ct & 1;
        if (ct < 7) {
            int c0 = (ct + 1) * 32;
            #pragma unroll
            for (int p = 0; p < 8; p++)
                zr[p] = zbase[(size_t)(c0 + zc + 4 * p) * 1024 + zn];
            #pragma unroll
            for (int p = 0; p < 4; p++)
                er[p] = *(const float4*)&e[(size_t)(n0 + enr + 32 * p) * CD + c0 + 4 * ec4];
        }

        #pragma unroll
        for (int kk = 0; kk < 32; kk++) {
            float4 a = *(const float4*)&zs[cur][kk][ty * 4];
            unsigned long long av0 = pack_dup(a.x);
            unsigned long long av1 = pack_dup(a.y);
            unsigned long long av2v = pack_dup(a.z);
            unsigned long long av3 = pack_dup(a.w);
            const float* erow = &es[cur][kk][0];
            int i0 = (2 * tx) ^ (kk & 28);
            unsigned long long bv0 = *(const unsigned long long*)(erow + i0);
            unsigned long long bv1 = *(const unsigned long long*)(erow + i0 + 32);
            unsigned long long bv2 = *(const unsigned long long*)(erow + i0 + 64);
            unsigned long long bv3 = *(const unsigned long long*)(erow + i0 + 96);
            fma2(acc2[0][0], av0, bv0); fma2(acc2[0][1], av0, bv1);
            fma2(acc2[0][2], av0, bv2); fma2(acc2[0][3], av0, bv3);
            fma2(acc2[1][0], av1, bv0); fma2(acc2[1][1], av1, bv1);
            fma2(acc2[1][2], av1, bv2); fma2(acc2[1][3], av1, bv3);
            fma2(acc2[2][0], av2v, bv0); fma2(acc2[2][1], av2v, bv1);
            fma2(acc2[2][2], av2v, bv2); fma2(acc2[2][3], av2v, bv3);
            fma2(acc2[3][0], av3, bv0); fma2(acc2[3][1], av3, bv1);
            fma2(acc2[3][2], av3, bv2); fma2(acc2[3][3], av3, bv3);
        }

        if (ct < 7) {
            int nxt = cur ^ 1;
            #pragma unroll
            for (int p = 0; p < 8; p++)
                zs[nxt][zc + 4 * p][zn] = zr[p];
            #pragma unroll
            for (int p = 0; p < 4; p++) {
                int nn = (enr + 32 * p) ^ swd;
                es[nxt][4 * ec4 + 0][nn] = er[p].x;
                es[nxt][4 * ec4 + 1][nn] = er[p].y;
                es[nxt][4 * ec4 + 2][nn] = er[p].z;
                es[nxt][4 * ec4 + 3][nn] = er[p].w;
            }
        }
        __syncthreads();
    }

    // epilogue: d = fl(fl(sz - 2m) + en), lexicographic argmin.  (FROZEN math)
    float* sdp = (float*)&zs[0][0][0];   // reuse smem (all compute done)
    int*   sip = (int*)&zs[1][0][0];

    #pragma unroll
    for (int i = 0; i < 4; i++) {
        int gm = m0 + ty * 4 + i;
        float szv = g_sz[gm];
        float bd = 3.402823466e+38f;
        int   bi = 0x7fffffff;
        #pragma unroll
        for (int q = 0; q < 4; q++) {
            float mlo, mhi;
            unpack2(acc2[i][q], mlo, mhi);
            int gn = n0 + 2 * tx + 32 * q;
            float dlo = __fadd_rn(__fsub_rn(szv, __fmul_rn(2.0f, mlo)), g_en[gn]);
            if (dlo < bd || (dlo == bd && gn < bi)) { bd = dlo; bi = gn; }
            float dhi = __fadd_rn(__fsub_rn(szv, __fmul_rn(2.0f, mhi)), g_en[gn + 1]);
            if (dhi < bd || (dhi == bd && gn + 1 < bi)) { bd = dhi; bi = gn + 1; }
        }
        sdp[(ty * 4 + i) * 17 + tx] = bd;
        sip[(ty * 4 + i) * 17 + tx] = bi;
    }
    __syncthreads();

    if (tid < 64) {
        float bd = sdp[tid * 17];
        int   bi = sip[tid * 17];
        #pragma unroll
        for (int t = 1; t < 16; t++) {
            float d  = sdp[tid * 17 + t];
            int   ii = sip[tid * 17 + t];
            if (d < bd || (d == bd && ii < bi)) { bd = d; bi = ii; }
        }
        int gm = m0 + tid;
        g_pd[(size_t)gm * NCHUNK + blockIdx.x] = bd;
        g_pi[(size_t)gm * NCHUNK + blockIdx.x] = bi;
    }
}

// ---------------------------------------------------------------------------
// Reduce 64 chunk candidates per token (chunks ascending => lower index wins
// ties via strict <), write index, histogram, float indices output.
// ---------------------------------------------------------------------------
__global__ __launch_bounds__(256) void k_reduce(float* __restrict__ out_idx,
                                                int write_idx) {
    int n = blockIdx.x * 256 + threadIdx.x;
    if (n >= NTOK) return;
    const float* pd = g_pd + (size_t)n * NCHUNK;
    const int*   pi = g_pi + (size_t)n * NCHUNK;
    float bd = pd[0];
    int   bi = pi[0];
    #pragma unroll 8
    for (int c = 1; c < NCHUNK; c++) {
        float d = pd[c];
        if (d < bd) { bd = d; bi = pi[c]; }
    }
    g_idx[n] = bi;
    atomicAdd(&g_hist[bi], 1u);
    if (write_idx) out_idx[n] = (float)bi;
}

// ---------------------------------------------------------------------------
// z_q_st = fl(z + fl(z_q - z)); per-block mse partial in double.
// ---------------------------------------------------------------------------
__global__ __launch_bounds__(1024) void k_zq(const float* __restrict__ z,
                                             const float* __restrict__ e,
                                             float* __restrict__ out) {
    __shared__ double red[1024];
    int f = blockIdx.x * 1024 + threadIdx.x;
    int bc = f >> 10;
    int hw = f & 1023;
    int bb = bc >> 8;
    int c  = bc & 255;
    int n  = bb * 1024 + hw;

    float zv = z[f];
    float zq = e[(size_t)g_idx[n] * CD + c];
    float t  = __fsub_rn(zq, zv);
    out[f]   = __fadd_rn(zv, t);
    float dm = __fsub_rn(zv, zq);
    red[threadIdx.x] = (double)dm * (double)dm;
    __syncthreads();
    for (int s = 512; s >= 1; s >>= 1) {
        if (threadIdx.x < s) red[threadIdx.x] += red[threadIdx.x + s];
        __syncthreads();
    }
    if (threadIdx.x == 0) g_msep[blockIdx.x] = red[0];
}

// ---------------------------------------------------------------------------
// Finalize: mse -> vq_loss, histogram -> perplexity. Deterministic.
// ---------------------------------------------------------------------------
__global__ __launch_bounds__(256) void k_final(float* __restrict__ out_scalars) {
    __shared__ double red[256];
    int t = threadIdx.x;

    double s = 0.0;
    for (int i = t; i < 8192; i += 256) s += g_msep[i];
    red[t] = s;
    __syncthreads();
    for (int st = 128; st >= 1; st >>= 1) {
        if (t < st) red[t] += red[t + st];
        __syncthreads();
    }
    double mse = red[0] / (double)NELEM;

    double ent = 0.0;
    for (int k = t; k < KCB; k += 256) {
        unsigned int c = g_hist[k];
        if (c) {
            double p = (double)c / (double)NTOK;
            ent += p * log(p);
        }
    }
    __syncthreads();
    red[t] = ent;
    __syncthreads();
    for (int st = 128; st >= 1; st >>= 1) {
        if (t < st) red[t] += red[t + st];
        __syncthreads();
    }
    if (t == 0) {
        out_scalars[0] = __fmul_rn(1.25f, (float)mse);   // (1 + cc) * mse
        out_scalars[1] = (float)exp(-red[0]);            // perplexity
    }
}

extern "C" void kernel_launch(void* const* d_in, const int* in_sizes, int n_in,
                              void* d_out, int out_size) {
    const float* z = (const float*)d_in[0];   // z_e  [32,256,32,32]
    const float* e = (const float*)d_in[1];   // emb_w [8192,256]
    float* out = (float*)d_out;

    // Layout: [z_q_st (8388608) | vq_loss | perplexity | indices (32768)]
    int full = (out_size >= NELEM + 2 + NTOK) ? 1 : 0;
    float* out_scalars = out + NELEM;
    float* out_idx     = out + NELEM + 2;

    k_sz<<<NTOK / 8, 256>>>(z);
    k_en<<<KCB * 32 / 256, 256>>>(e);
    {
        dim3 grid(KCB / 128, NTOK / 64);
        k_dist<<<grid, 256>>>(z, e);
    }
    k_reduce<<<NTOK / 256, 256>>>(full ? out_idx : (float*)d_out, full);
    k_zq<<<NELEM / 1024, 1024>>>(z, e, out);
    if (full) k_final<<<1, 256>>>(out_scalars);
}

// round 10
// speedup vs baseline: 2.8165x; 1.7300x over previous
#include <cuda_runtime.h>
#include <cuda_bf16.h>
#include <cstdint>

#define CD    256
#define NTOK  32768
#define KCB   8192
#define NELEM 8388608
#define NTILE 64          // KCB / 128
#define WIN   4e-4f       // candidate window (>= 2 * |d~ - d| bound)
#define OVCAP (1 << 21)   // 2M overflow entries

__device__ float g_sz[NTOK];
__device__ float g_en[KCB];
__device__ unsigned long long g_tk[(size_t)NTOK * NTILE]; // per-(token,tile) approx best key
__device__ unsigned long long g_bk[NTOK];                 // exact best key
__device__ float g_th[NTOK];                              // d~min + WIN
__device__ int   g_idx[NTOK];
__device__ unsigned int g_hist[KCB];
__device__ double g_msep[8192];
__device__ __nv_bfloat16 g_zb[(size_t)NTOK * CD];
__device__ __nv_bfloat16 g_eb[(size_t)KCB * CD];
__device__ int  g_ovcnt;
__device__ int4 g_ov[OVCAP];   // {token, code, d~bits, 0}

// ---------------- PTX helpers ----------------
__device__ __forceinline__ void cp16(uint32_t dst, const void* src) {
    asm volatile("cp.async.cg.shared.global [%0], [%1], 16;\n" :: "r"(dst), "l"(src));
}
__device__ __forceinline__ void cp_commit() { asm volatile("cp.async.commit_group;\n" ::); }
__device__ __forceinline__ void cp_wait0()  { asm volatile("cp.async.wait_group 0;\n" ::); }
__device__ __forceinline__ void ldsm4(uint32_t& r0, uint32_t& r1, uint32_t& r2, uint32_t& r3,
                                      uint32_t a) {
    asm volatile("ldmatrix.sync.aligned.m8n8.x4.shared.b16 {%0,%1,%2,%3}, [%4];"
                 : "=r"(r0), "=r"(r1), "=r"(r2), "=r"(r3) : "r"(a));
}
__device__ __forceinline__ void mma16816(float* c, const uint32_t* a, const uint32_t* b) {
    asm volatile("mma.sync.aligned.m16n8k16.row.col.f32.bf16.bf16.f32 "
                 "{%0,%1,%2,%3},{%4,%5,%6,%7},{%8,%9},{%0,%1,%2,%3};"
                 : "+f"(c[0]), "+f"(c[1]), "+f"(c[2]), "+f"(c[3])
                 : "r"(a[0]), "r"(a[1]), "r"(a[2]), "r"(a[3]), "r"(b[0]), "r"(b[1]));
}

// async-copy one K-chunk (64 bf16) of the 128-row A and B tiles into buffer buf
__device__ __forceinline__ void issue_chunk(uint32_t sA_u, uint32_t sB_u,
                                            int buf, int kc, int m0, int n0,
                                            int r_ld, int s_ld) {
    #pragma unroll
    for (int q = 0; q < 4; q++) {
        int r = r_ld + 32 * q;
        int sw = (s_ld ^ (r & 7));
        const uint4* gA = (const uint4*)g_zb + (size_t)(m0 + r) * 32 + kc * 8 + s_ld;
        cp16(sA_u + buf * 16384 + (r * 8 + sw) * 16, gA);
        const uint4* gB = (const uint4*)g_eb + (size_t)(n0 + r) * 32 + kc * 8 + s_ld;
        cp16(sB_u + buf * 16384 + (r * 8 + sw) * 16, gB);
    }
    cp_commit();
}

// ---------------------------------------------------------------------------
// sz[n] = sum_c z[n,c]^2 — FROZEN (bit-exact decision-path input).
// ---------------------------------------------------------------------------
__global__ __launch_bounds__(256) void k_sz(const float* __restrict__ z) {
    __shared__ float zt[CD][9];
    int n0 = blockIdx.x * 8;
    int b  = n0 >> 10;
    int hw0 = n0 & 1023;
    const float* zbase = z + (size_t)b * 262144 + hw0;

    int wpos  = threadIdx.x & 7;
    int cbase = threadIdx.x >> 3;
    #pragma unroll
    for (int j = 0; j < 8; j++) {
        int c = cbase + 32 * j;
        zt[c][wpos] = zbase[(size_t)c * 1024 + wpos];
    }
    __syncthreads();

    int warp = threadIdx.x >> 5;
    int lane = threadIdx.x & 31;
    float p = 0.0f;
    #pragma unroll
    for (int j = 0; j < 8; j++) {
        float v = zt[lane + 32 * j][warp];
        p = __fadd_rn(p, __fmul_rn(v, v));
    }
    #pragma unroll
    for (int off = 16; off >= 1; off >>= 1)
        p = __fadd_rn(p, __shfl_down_sync(0xffffffffu, p, off));
    if (lane == 0) g_sz[n0 + warp] = p;
}

// ---------------------------------------------------------------------------
// en[k] = sum_c e[k,c]^2 — FROZEN. Also zeroes hist and overflow counter.
// ---------------------------------------------------------------------------
__global__ __launch_bounds__(256) void k_en(const float* __restrict__ e) {
    int gt = blockIdx.x * 256 + threadIdx.x;
    if (gt < KCB) g_hist[gt] = 0u;
    if (gt == 0)  g_ovcnt = 0;

    int warp = gt >> 5;
    int lane = gt & 31;
    if (warp < KCB) {
        const float* row = e + (size_t)warp * CD;
        float p = 0.0f;
        #pragma unroll
        for (int j = 0; j < 8; j++) {
            float v = row[lane + 32 * j];
            p = __fadd_rn(p, __fmul_rn(v, v));
        }
        #pragma unroll
        for (int off = 16; off >= 1; off >>= 1)
            p = __fadd_rn(p, __shfl_down_sync(0xffffffffu, p, off));
        if (lane == 0) g_en[warp] = p;
    }
}

// ---------------------------------------------------------------------------
// z -> bf16 tokens-major [NTOK][256] (transpose via smem). Also init g_bk.
// ---------------------------------------------------------------------------
__global__ __launch_bounds__(256) void k_cvtz(const float* __restrict__ z) {
    __shared__ __nv_bfloat16 sb[8][264];
    int n0 = blockIdx.x * 8;
    const float* zbase = z + (size_t)(n0 >> 10) * 262144 + (n0 & 1023);
    int w = threadIdx.x & 7, c0 = threadIdx.x >> 3;
    #pragma unroll
    for (int j = 0; j < 8; j++) {
        int c = c0 + 32 * j;
        sb[w][c] = __float2bfloat16(zbase[(size_t)c * 1024 + w]);
    }
    if (threadIdx.x < 8) g_bk[n0 + threadIdx.x] = ~0ull;
    __syncthreads();
    int tt = threadIdx.x >> 5, cc = (threadIdx.x & 31) * 8;
    *(uint4*)&g_zb[(size_t)(n0 + tt) * CD + cc] = *(uint4*)&sb[tt][cc];
}

// ---------------------------------------------------------------------------
// e -> bf16 [KCB][256].
// ---------------------------------------------------------------------------
__global__ __launch_bounds__(256) void k_cvte(const float* __restrict__ e) {
    size_t i = ((size_t)blockIdx.x * 256 + threadIdx.x) * 8;
    float4 v0 = *(const float4*)(e + i);
    float4 v1 = *(const float4*)(e + i + 4);
    __nv_bfloat16 t[8];
    t[0] = __float2bfloat16(v0.x); t[1] = __float2bfloat16(v0.y);
    t[2] = __float2bfloat16(v0.z); t[3] = __float2bfloat16(v0.w);
    t[4] = __float2bfloat16(v1.x); t[5] = __float2bfloat16(v1.y);
    t[6] = __float2bfloat16(v1.z); t[7] = __float2bfloat16(v1.w);
    *(uint4*)&g_eb[i] = *(uint4*)t;
}

// ---------------------------------------------------------------------------
// Approximate distance GEMM (bf16 HMMA) + per-(token,tile) pruning.
// Block = 128 tokens x 128 codes, K=256 in 4 chunks of 64 (cp.async db).
// Warps 4(m) x 2(n); warp tile 32x64; mma.m16n8k16.
// Keeps per (token,tile) best key (d~bits<<32|idx) and appends every value
// with d~ <= tilemin + WIN to the overflow list (superset of all survivors).
// ---------------------------------------------------------------------------
__global__ __launch_bounds__(256, 2) void k_gemm() {
    extern __shared__ char smem[];
    __nv_bfloat16* sA = (__nv_bfloat16*)smem;              // 2 x 16KB
    __nv_bfloat16* sB = (__nv_bfloat16*)(smem + 32768);    // 2 x 16KB
    float* s_en = (float*)(smem + 65536);
    float* s_sz = (float*)(smem + 66048);
    unsigned long long* s_key = (unsigned long long*)(smem + 66560);

    int tid = threadIdx.x;
    int n0 = blockIdx.x * 128, m0 = blockIdx.y * 128;
    if (tid < 128) {
        s_en[tid] = g_en[n0 + tid];
        s_sz[tid] = g_sz[m0 + tid];
        s_key[tid] = ~0ull;
    }

    int l = tid & 31, w = tid >> 5;
    int wy = w & 3, wx = w >> 2;
    uint32_t sA_u = (uint32_t)__cvta_generic_to_shared(sA);
    uint32_t sB_u = (uint32_t)__cvta_generic_to_shared(sB);

    int r_ld = tid >> 3, s_ld = tid & 7;

    float acc[2][8][4];
    #pragma unroll
    for (int mf = 0; mf < 2; mf++)
        #pragma unroll
        for (int nf = 0; nf < 8; nf++)
            #pragma unroll
            for (int u = 0; u < 4; u++) acc[mf][nf][u] = 0.0f;

    issue_chunk(sA_u, sB_u, 0, 0, m0, n0, r_ld, s_ld);
    cp_wait0();
    __syncthreads();

    for (int kc = 0; kc < 4; kc++) {
        int cur = kc & 1;
        if (kc < 3) issue_chunk(sA_u, sB_u, cur ^ 1, kc + 1, m0, n0, r_ld, s_ld);

        #pragma unroll
        for (int j = 0; j < 4; j++) {
            int seg = 2 * j + (l >> 4);
            uint32_t a[2][4];
            #pragma unroll
            for (int mf = 0; mf < 2; mf++) {
                int rr = wy * 32 + mf * 16 + (l & 15);
                ldsm4(a[mf][0], a[mf][1], a[mf][2], a[mf][3],
                      sA_u + cur * 16384 + (rr * 8 + (seg ^ (rr & 7))) * 16);
            }
            uint32_t b[8][2];
            #pragma unroll
            for (int p = 0; p < 4; p++) {
                int rr = wx * 64 + p * 16 + (l & 15);
                uint32_t r0, r1, r2, r3;
                ldsm4(r0, r1, r2, r3,
                      sB_u + cur * 16384 + (rr * 8 + (seg ^ (rr & 7))) * 16);
                b[2 * p][0] = r0; b[2 * p + 1][0] = r1;
                b[2 * p][1] = r2; b[2 * p + 1][1] = r3;
            }
            #pragma unroll
            for (int mf = 0; mf < 2; mf++)
                #pragma unroll
                for (int nf = 0; nf < 8; nf++)
                    mma16816(acc[mf][nf], a[mf], b[nf]);
        }
        if (kc < 3) cp_wait0();
        __syncthreads();
    }

    // ---- epilogue: d~ = fl(fl(sz - fl(2m~)) + en); per-row min + overflow ----
    int t4 = l & 3, g8 = l >> 2;

    #pragma unroll
    for (int mf = 0; mf < 2; mf++) {
        #pragma unroll
        for (int hl = 0; hl < 2; hl++) {
            int row_l = wy * 32 + mf * 16 + hl * 8 + g8;
            float szv = s_sz[row_l];
            unsigned long long best = ~0ull;
            #pragma unroll
            for (int nf = 0; nf < 8; nf++) {
                #pragma unroll
                for (int u = 0; u < 2; u++) {
                    int col_l = wx * 64 + nf * 8 + 2 * t4 + u;
                    float mt = acc[mf][nf][hl * 2 + u];
                    float d = __fadd_rn(__fsub_rn(szv, __fmul_rn(2.0f, mt)), s_en[col_l]);
                    acc[mf][nf][hl * 2 + u] = d;
                    unsigned long long key =
                        ((unsigned long long)__float_as_uint(d) << 32) |
                        (unsigned int)(n0 + col_l);
                    if (key < best) best = key;
                }
            }
            best = min(best, __shfl_xor_sync(0xffffffffu, best, 1));
            best = min(best, __shfl_xor_sync(0xffffffffu, best, 2));
            if (t4 == 0) atomicMin(&s_key[row_l], best);
        }
    }
    __syncthreads();

    #pragma unroll
    for (int mf = 0; mf < 2; mf++) {
        #pragma unroll
        for (int hl = 0; hl < 2; hl++) {
            int row_l = wy * 32 + mf * 16 + hl * 8 + g8;
            unsigned long long bk = s_key[row_l];
            float th = __fadd_rn(__uint_as_float((uint32_t)(bk >> 32)), WIN);
            #pragma unroll
            for (int nf = 0; nf < 8; nf++) {
                #pragma unroll
                for (int u = 0; u < 2; u++) {
                    float d = acc[mf][nf][hl * 2 + u];
                    int gidx = n0 + wx * 64 + nf * 8 + 2 * t4 + u;
                    unsigned long long key =
                        ((unsigned long long)__float_as_uint(d) << 32) | (unsigned int)gidx;
                    if (d <= th && key != bk) {
                        int pos = atomicAdd(&g_ovcnt, 1);
                        if (pos < OVCAP)
                            g_ov[pos] = make_int4(m0 + row_l, gidx, __float_as_int(d), 0);
                    }
                }
            }
        }
    }

    if (tid < 128)
        g_tk[(size_t)(m0 + tid) * NTILE + blockIdx.x] = s_key[tid];
}

// ---------------------------------------------------------------------------
// Exact distance (FROZEN): single fmaf chain c ascending, exact epilogue.
// ---------------------------------------------------------------------------
__device__ __forceinline__ float rescore(const float* __restrict__ z,
                                         const float* __restrict__ e,
                                         int n, int k) {
    int b = n >> 10, hw = n & 1023;
    const float* zr = z + (size_t)b * 262144 + hw;
    const float* er = e + (size_t)k * CD;
    float m = 0.0f;
    #pragma unroll 8
    for (int c = 0; c < CD; c++)
        m = __fmaf_rn(zr[(size_t)c * 1024], er[c], m);
    return __fadd_rn(__fsub_rn(g_sz[n], __fmul_rn(2.0f, m)), g_en[k]);
}

// ---------------------------------------------------------------------------
// Per token: global approx min over tiles, rescore qualifying tile winners.
// ---------------------------------------------------------------------------
__global__ __launch_bounds__(256) void k_reduce2(const float* __restrict__ z,
                                                 const float* __restrict__ e) {
    int n = blockIdx.x * 256 + threadIdx.x;
    if (n >= NTOK) return;
    const unsigned long long* tk = g_tk + (size_t)n * NTILE;
    unsigned long long am = ~0ull;
    #pragma unroll 8
    for (int t = 0; t < NTILE; t++) am = min(am, tk[t]);
    float th = __fadd_rn(__uint_as_float((uint32_t)(am >> 32)), WIN);
    g_th[n] = th;

    unsigned long long best = ~0ull;
    for (int t = 0; t < NTILE; t++) {
        unsigned long long k = tk[t];
        if (__uint_as_float((uint32_t)(k >> 32)) <= th) {
            int idx = (int)(k & 0xffffffffull);
            float d = rescore(z, e, n, idx);
            unsigned long long key =
                ((unsigned long long)__float_as_uint(d) << 32) | (unsigned int)idx;
            if (key < best) best = key;
        }
    }
    g_bk[n] = best;
}

// ---------------------------------------------------------------------------
// Rescore qualifying overflow candidates, merge via atomicMin on exact keys.
// ---------------------------------------------------------------------------
__global__ __launch_bounds__(256) void k_over(const float* __restrict__ z,
                                              const float* __restrict__ e) {
    int i = blockIdx.x * 256 + threadIdx.x;
    int cnt = g_ovcnt;
    if (cnt > OVCAP) cnt = OVCAP;
    if (i >= cnt) return;
    int4 ev = g_ov[i];
    if (__int_as_float(ev.z) <= g_th[ev.x]) {
        float d = rescore(z, e, ev.x, ev.y);
        unsigned long long key =
            ((unsigned long long)__float_as_uint(d) << 32) | (unsigned int)ev.y;
        atomicMin(&g_bk[ev.x], key);
    }
}

// ---------------------------------------------------------------------------
// Finalize indices: g_idx, histogram, float index output.
// ---------------------------------------------------------------------------
__global__ __launch_bounds__(256) void k_hist(float* __restrict__ out_idx, int write_idx) {
    int n = blockIdx.x * 256 + threadIdx.x;
    if (n >= NTOK) return;
    int idx = (int)(g_bk[n] & 0xffffffffull);
    g_idx[n] = idx;
    atomicAdd(&g_hist[idx], 1u);
    if (write_idx) out_idx[n] = (float)idx;
}

// ---------------------------------------------------------------------------
// z_q_st = fl(z + fl(z_q - z)); per-block mse partial in double.  (FROZEN)
// ---------------------------------------------------------------------------
__global__ __launch_bounds__(1024) void k_zq(const float* __restrict__ z,
                                             const float* __restrict__ e,
                                             float* __restrict__ out) {
    __shared__ double red[1024];
    int f = blockIdx.x * 1024 + threadIdx.x;
    int bc = f >> 10;
    int hw = f & 1023;
    int bb = bc >> 8;
    int c  = bc & 255;
    int n  = bb * 1024 + hw;

    float zv = z[f];
    float zq = e[(size_t)g_idx[n] * CD + c];
    float t  = __fsub_rn(zq, zv);
    out[f]   = __fadd_rn(zv, t);
    float dm = __fsub_rn(zv, zq);
    red[threadIdx.x] = (double)dm * (double)dm;
    __syncthreads();
    for (int s = 512; s >= 1; s >>= 1) {
        if (threadIdx.x < s) red[threadIdx.x] += red[threadIdx.x + s];
        __syncthreads();
    }
    if (threadIdx.x == 0) g_msep[blockIdx.x] = red[0];
}

__global__ __launch_bounds__(256) void k_final(float* __restrict__ out_scalars) {
    __shared__ double red[256];
    int t = threadIdx.x;

    double s = 0.0;
    for (int i = t; i < 8192; i += 256) s += g_msep[i];
    red[t] = s;
    __syncthreads();
    for (int st = 128; st >= 1; st >>= 1) {
        if (t < st) red[t] += red[t + st];
        __syncthreads();
    }
    double mse = red[0] / (double)NELEM;

    double ent = 0.0;
    for (int k = t; k < KCB; k += 256) {
        unsigned int c = g_hist[k];
        if (c) {
            double p = (double)c / (double)NTOK;
            ent += p * log(p);
        }
    }
    __syncthreads();
    red[t] = ent;
    __syncthreads();
    for (int st = 128; st >= 1; st >>= 1) {
        if (t < st) red[t] += red[t + st];
        __syncthreads();
    }
    if (t == 0) {
        out_scalars[0] = __fmul_rn(1.25f, (float)mse);
        out_scalars[1] = (float)exp(-red[0]);
    }
}

extern "C" void kernel_launch(void* const* d_in, const int* in_sizes, int n_in,
                              void* d_out, int out_size) {
    const float* z = (const float*)d_in[0];
    const float* e = (const float*)d_in[1];
    float* out = (float*)d_out;

    int full = (out_size >= NELEM + 2 + NTOK) ? 1 : 0;
    float* out_scalars = out + NELEM;
    float* out_idx     = out + NELEM + 2;

    cudaFuncSetAttribute(k_gemm, cudaFuncAttributeMaxDynamicSharedMemorySize, 67584);

    k_sz<<<NTOK / 8, 256>>>(z);
    k_en<<<KCB * 32 / 256, 256>>>(e);
    k_cvtz<<<NTOK / 8, 256>>>(z);
    k_cvte<<<(KCB * CD / 8) / 256, 256>>>(e);
    {
        dim3 grid(KCB / 128, NTOK / 128);
        k_gemm<<<grid, 256, 67584>>>();
    }
    k_reduce2<<<NTOK / 256, 256>>>(z, e);
    k_over<<<OVCAP / 256, 256>>>(z, e);
    k_hist<<<NTOK / 256, 256>>>(full ? out_idx : (float*)d_out, full);
    k_zq<<<NELEM / 1024, 1024>>>(z, e, out);
    if (full) k_final<<<1, 256>>>(out_scalars);
}